// round 1
// baseline (speedup 1.0000x reference)
#include <cuda_runtime.h>

#define SEQ   2048
#define DM    2048
#define NH    32
#define DH    64
#define CK    128
#define NC    16
#define BZ    4
#define MROWS (BZ*SEQ)   // 8192

// ---------------- scratch (device globals; no allocation) ----------------
__device__ float g_xn [BZ*SEQ*DM];
__device__ float g_rx [BZ*SEQ*DM];
__device__ float g_kx [BZ*SEQ*DM];
__device__ float g_vx [BZ*SEQ*DM];
__device__ float g_r  [BZ*SEQ*DM];
__device__ float g_k  [BZ*SEQ*DM];
__device__ float g_v  [BZ*SEQ*DM];
__device__ float g_att[BZ*SEQ*DM];
__device__ float g_rkw[(size_t)BZ*NC*NH*CK*CK];   // 33.5M floats

// ---------------- LN over D_MODEL, also emits xn[:, -1, :] ----------------
__global__ void ln1_kernel(const float* __restrict__ x,
                           const float* __restrict__ sc,
                           const float* __restrict__ bi,
                           float* __restrict__ xlast)
{
    int row = blockIdx.x;                 // b*SEQ + t
    const float* xr = x + (size_t)row * DM;
    float* yr = g_xn + (size_t)row * DM;
    float vals[8];
    float s = 0.f, q = 0.f;
#pragma unroll
    for (int i = 0; i < 8; i++) {
        float v = xr[threadIdx.x + i * 256];
        vals[i] = v; s += v; q += v * v;
    }
#pragma unroll
    for (int o = 16; o > 0; o >>= 1) {
        s += __shfl_xor_sync(0xffffffffu, s, o);
        q += __shfl_xor_sync(0xffffffffu, q, o);
    }
    __shared__ float rs[8], rq[8];
    int w = threadIdx.x >> 5;
    if ((threadIdx.x & 31) == 0) { rs[w] = s; rq[w] = q; }
    __syncthreads();
    s = 0.f; q = 0.f;
#pragma unroll
    for (int i = 0; i < 8; i++) { s += rs[i]; q += rq[i]; }
    float mu  = s * (1.f / DM);
    float inv = rsqrtf(q * (1.f / DM) - mu * mu + 1e-5f);
    bool last = ((row & (SEQ - 1)) == SEQ - 1);
#pragma unroll
    for (int i = 0; i < 8; i++) {
        int c = threadIdx.x + i * 256;
        float y = (vals[i] - mu) * inv * sc[c] + bi[c];
        yr[c] = y;
        if (last) xlast[(row >> 11) * DM + c] = y;
    }
}

// ---------------- token-shift mixing ----------------
__global__ void mix_kernel(const float4* __restrict__ tmr,
                           const float4* __restrict__ tmk,
                           const float4* __restrict__ tmv)
{
    long i = (long)blockIdx.x * blockDim.x + threadIdx.x;   // float4 index
    const float4* xn4 = (const float4*)g_xn;
    int col = (int)(i & 511);
    long t  = (i >> 9) & (SEQ - 1);
    float4 cur = xn4[i];
    float4 prv = (t == 0) ? make_float4(0.f,0.f,0.f,0.f) : xn4[i - 512];
    float4 mr = tmr[col], mk = tmk[col], mv = tmv[col];
    float4 o;
    o.x = cur.x*mr.x + (1.f-mr.x)*prv.x;
    o.y = cur.y*mr.y + (1.f-mr.y)*prv.y;
    o.z = cur.z*mr.z + (1.f-mr.z)*prv.z;
    o.w = cur.w*mr.w + (1.f-mr.w)*prv.w;
    ((float4*)g_rx)[i] = o;
    o.x = cur.x*mk.x + (1.f-mk.x)*prv.x;
    o.y = cur.y*mk.y + (1.f-mk.y)*prv.y;
    o.z = cur.z*mk.z + (1.f-mk.z)*prv.z;
    o.w = cur.w*mk.w + (1.f-mk.w)*prv.w;
    ((float4*)g_kx)[i] = o;
    o.x = cur.x*mv.x + (1.f-mv.x)*prv.x;
    o.y = cur.y*mv.y + (1.f-mv.y)*prv.y;
    o.z = cur.z*mv.z + (1.f-mv.z)*prv.z;
    o.w = cur.w*mv.w + (1.f-mv.w)*prv.w;
    ((float4*)g_vx)[i] = o;
}

// ---------------- SGEMM 128x128x8, 256 thr, 8x8 micro-tile ----------------
// MODE 0: g_rx@W -> g_r | 1: g_kx@W -> g_k | 2: g_vx@W -> g_v
// MODE 3: g_att@W + Add -> Out
template<int MODE>
__global__ void sgemm_kernel(const float* __restrict__ W,
                             const float* __restrict__ Add,
                             float* __restrict__ Out)
{
    const float* A;
    float* C;
    if constexpr (MODE == 0) { A = g_rx; C = g_r; }
    else if constexpr (MODE == 1) { A = g_kx; C = g_k; }
    else if constexpr (MODE == 2) { A = g_vx; C = g_v; }
    else { A = g_att; C = Out; }

    __shared__ float As[8][128];
    __shared__ float Bs[8][128];
    int tid = threadIdx.x;
    int bm = blockIdx.y * 128, bn = blockIdx.x * 128;
    int arow = tid >> 1,  acol = (tid & 1) << 2;
    int brow = tid >> 5,  bcol = (tid & 31) << 2;
    const float* Ap = A + (size_t)(bm + arow) * DM + acol;
    const float* Bp = W + (size_t)brow * DM + bn + bcol;
    int tx = tid & 15, ty = tid >> 4;
    float acc[8][8] = {};
    for (int k0 = 0; k0 < DM; k0 += 8) {
        float4 av = *(const float4*)Ap;
        float4 bv = *(const float4*)Bp;
        As[acol + 0][arow] = av.x;
        As[acol + 1][arow] = av.y;
        As[acol + 2][arow] = av.z;
        As[acol + 3][arow] = av.w;
        *(float4*)&Bs[brow][bcol] = bv;
        __syncthreads();
#pragma unroll
        for (int kk = 0; kk < 8; kk++) {
            float4 a0 = *(const float4*)&As[kk][ty * 8];
            float4 a1 = *(const float4*)&As[kk][ty * 8 + 4];
            float4 b0 = *(const float4*)&Bs[kk][tx * 8];
            float4 b1 = *(const float4*)&Bs[kk][tx * 8 + 4];
            float ar[8] = {a0.x,a0.y,a0.z,a0.w,a1.x,a1.y,a1.z,a1.w};
            float br[8] = {b0.x,b0.y,b0.z,b0.w,b1.x,b1.y,b1.z,b1.w};
#pragma unroll
            for (int i = 0; i < 8; i++)
#pragma unroll
                for (int j = 0; j < 8; j++)
                    acc[i][j] += ar[i] * br[j];
        }
        __syncthreads();
        Ap += 8;
        Bp += (size_t)8 * DM;
    }
#pragma unroll
    for (int i = 0; i < 8; i++) {
        size_t ro = (size_t)(bm + ty * 8 + i) * DM + bn + tx * 8;
#pragma unroll
        for (int j = 0; j < 8; j += 4) {
            float4 v;
            v.x = acc[i][j]; v.y = acc[i][j+1]; v.z = acc[i][j+2]; v.w = acc[i][j+3];
            if constexpr (MODE == 3) {
                float4 a = *(const float4*)(Add + ro + j);
                v.x += a.x; v.y += a.y; v.z += a.z; v.w += a.w;
            }
            *(float4*)(C + ro + j) = v;
        }
    }
}

// ---------------- rkw = (r @ k^T) * mask, per (b,chunk,head), 64x64 tiles --
__global__ void rkw_kernel(const float* __restrict__ tdcy,
                           const float* __restrict__ tfirst)
{
    int jt = blockIdx.x, it = blockIdx.y, bch = blockIdx.z;
    int h = bch & 31;
    int chunk = (bch >> 5) & 15;
    int b = bch >> 9;
    __shared__ float rs[64][68];   // [d][i]
    __shared__ float ks[64][68];   // [d][j]
    int tid = threadIdx.x;
    int lrow = tid >> 2;           // 0..63
    int lc4  = (tid & 3) * 16;     // d start
    size_t rbase = ((size_t)(b*SEQ + chunk*CK + it*64 + lrow)) * DM + h*64 + lc4;
    size_t kbase = ((size_t)(b*SEQ + chunk*CK + jt*64 + lrow)) * DM + h*64 + lc4;
#pragma unroll
    for (int m = 0; m < 4; m++) {
        float4 rv = *(const float4*)(g_r + rbase + m * 4);
        float4 kv = *(const float4*)(g_k + kbase + m * 4);
        int d = lc4 + m * 4;
        rs[d+0][lrow] = rv.x; rs[d+1][lrow] = rv.y; rs[d+2][lrow] = rv.z; rs[d+3][lrow] = rv.w;
        ks[d+0][lrow] = kv.x; ks[d+1][lrow] = kv.y; ks[d+2][lrow] = kv.z; ks[d+3][lrow] = kv.w;
    }
    __syncthreads();
    int tx = tid & 15, ty = tid >> 4;
    float acc[4][4] = {};
#pragma unroll 8
    for (int d = 0; d < 64; d++) {
        float4 a = *(const float4*)&rs[d][ty * 4];
        float4 bq = *(const float4*)&ks[d][tx * 4];
        float ar[4] = {a.x,a.y,a.z,a.w};
        float br[4] = {bq.x,bq.y,bq.z,bq.w};
#pragma unroll
        for (int x = 0; x < 4; x++)
#pragma unroll
            for (int y = 0; y < 4; y++)
                acc[x][y] += ar[x] * br[y];
    }
    float logw = -expf(tdcy[h]);
    float u    =  expf(tfirst[h]);
#pragma unroll
    for (int x = 0; x < 4; x++)
#pragma unroll
        for (int y = 0; y < 4; y++) {
            int i = it * 64 + ty * 4 + x;
            int j = jt * 64 + tx * 4 + y;
            float m;
            if (i > j)      m = expf(logw * (float)(i - j - 1));
            else if (i == j) m = u;
            else             m = 0.f;
            g_rkw[((size_t)bch * CK + i) * CK + j] = acc[x][y] * m;
        }
}

// ---------------- sep = rkw @ v, per (b,chunk,head) ----------------
__global__ void sep_kernel()
{
    int bch = blockIdx.x;
    int h = bch & 31;
    int chunk = (bch >> 5) & 15;
    int b = bch >> 9;
    int tid = threadIdx.x;
    __shared__ float vs[128][64];
    __shared__ float rk[16][132];   // [jj][i]
    {
        int row = tid >> 1, e0 = (tid & 1) * 32;
        size_t base = ((size_t)(b*SEQ + chunk*CK + row)) * DM + h*64 + e0;
#pragma unroll
        for (int m = 0; m < 8; m++)
            *(float4*)&vs[row][e0 + m * 4] = *(const float4*)(g_v + base + m * 4);
    }
    int ty = tid >> 3, tx = tid & 7;   // ty: 0..31 row groups, tx: 0..7 col groups
    float acc[4][8] = {};
    int rrow = tid >> 1, jc = (tid & 1) * 8;
    for (int s = 0; s < 8; s++) {
        const float* src = g_rkw + ((size_t)bch * CK + rrow) * CK + s * 16 + jc;
        float4 r0 = *(const float4*)src;
        float4 r1 = *(const float4*)(src + 4);
        __syncthreads();    // protect prev-iter readers of rk (also orders vs on s==0)
        rk[jc+0][rrow] = r0.x; rk[jc+1][rrow] = r0.y; rk[jc+2][rrow] = r0.z; rk[jc+3][rrow] = r0.w;
        rk[jc+4][rrow] = r1.x; rk[jc+5][rrow] = r1.y; rk[jc+6][rrow] = r1.z; rk[jc+7][rrow] = r1.w;
        __syncthreads();
#pragma unroll
        for (int jj = 0; jj < 16; jj++) {
            float4 a  = *(const float4*)&rk[jj][ty * 4];
            float4 b0 = *(const float4*)&vs[s * 16 + jj][tx * 8];
            float4 b1 = *(const float4*)&vs[s * 16 + jj][tx * 8 + 4];
            float ar[4] = {a.x,a.y,a.z,a.w};
            float br[8] = {b0.x,b0.y,b0.z,b0.w,b1.x,b1.y,b1.z,b1.w};
#pragma unroll
            for (int x = 0; x < 4; x++)
#pragma unroll
                for (int e = 0; e < 8; e++)
                    acc[x][e] += ar[x] * br[e];
        }
    }
    size_t obase = ((size_t)(b*SEQ + chunk*CK)) * DM + h*64;
#pragma unroll
    for (int x = 0; x < 4; x++) {
        size_t ro = obase + (size_t)(ty * 4 + x) * DM + tx * 8;
        float4 o0, o1;
        o0.x = acc[x][0]; o0.y = acc[x][1]; o0.z = acc[x][2]; o0.w = acc[x][3];
        o1.x = acc[x][4]; o1.y = acc[x][5]; o1.z = acc[x][6]; o1.w = acc[x][7];
        *(float4*)(g_att + ro)     = o0;
        *(float4*)(g_att + ro + 4) = o1;
    }
}

// ---------------- sequential chunk scan per (b,head) ----------------
__global__ void scan_kernel(const float* __restrict__ tdcy,
                            float* __restrict__ state_out)
{
    int bh = blockIdx.x;
    int h = bh & 31, b = bh >> 5;
    int tid = threadIdx.x;
    __shared__ float state[64][65];
    __shared__ float bufA[32][68];
    __shared__ float bufB[32][68];
    float logw = -expf(tdcy[h]);
    float wC = expf(logw * 128.f);
    for (int idx = tid; idx < 64 * 64; idx += 256)
        state[idx >> 6][idx & 63] = 0.f;
    __syncthreads();
    int lrow = tid >> 3, lcol = (tid & 7) * 8;
    int td = (tid >> 4) * 4, te2 = (tid & 15) * 4;
    for (int c = 0; c < NC; c++) {
        size_t base = ((size_t)(b*SEQ + c*CK)) * DM + h * 64;
        // ---- bias = (r @ state) * w^i added into att (old state) ----
        for (int s4 = 0; s4 < 4; s4++) {
            const float* src = g_r + base + (size_t)(s4 * 32 + lrow) * DM + lcol;
            float4 v0 = *(const float4*)src;
            float4 v1 = *(const float4*)(src + 4);
            *(float4*)&bufA[lrow][lcol]     = v0;
            *(float4*)&bufA[lrow][lcol + 4] = v1;
            __syncthreads();
            float acc[8] = {};
            int ti = tid >> 3, te = (tid & 7) * 8;
#pragma unroll 8
            for (int d = 0; d < 64; d++) {
                float rv = bufA[ti][d];
#pragma unroll
                for (int e = 0; e < 8; e++)
                    acc[e] += rv * state[d][te + e];
            }
            float wi = expf(logw * (float)(s4 * 32 + ti));
            float* dst = g_att + base + (size_t)(s4 * 32 + ti) * DM + te;
            float4 o0 = *(float4*)dst;
            float4 o1 = *(float4*)(dst + 4);
            o0.x += wi * acc[0]; o0.y += wi * acc[1]; o0.z += wi * acc[2]; o0.w += wi * acc[3];
            o1.x += wi * acc[4]; o1.y += wi * acc[5]; o1.z += wi * acc[6]; o1.w += wi * acc[7];
            *(float4*)dst = o0;
            *(float4*)(dst + 4) = o1;
            __syncthreads();
        }
        // ---- state = state*w^C + (k * w^{C-1-j})^T @ v ----
        float sacc[4][4] = {};
        for (int s4 = 0; s4 < 4; s4++) {
            int j = s4 * 32 + lrow;
            float wk = expf(logw * (float)(127 - j));
            const float* ksrc = g_k + base + (size_t)j * DM + lcol;
            const float* vsrc = g_v + base + (size_t)j * DM + lcol;
            float4 k0 = *(const float4*)ksrc;
            float4 k1 = *(const float4*)(ksrc + 4);
            float4 w0 = *(const float4*)vsrc;
            float4 w1 = *(const float4*)(vsrc + 4);
            k0.x *= wk; k0.y *= wk; k0.z *= wk; k0.w *= wk;
            k1.x *= wk; k1.y *= wk; k1.z *= wk; k1.w *= wk;
            *(float4*)&bufA[lrow][lcol]     = k0;
            *(float4*)&bufA[lrow][lcol + 4] = k1;
            *(float4*)&bufB[lrow][lcol]     = w0;
            *(float4*)&bufB[lrow][lcol + 4] = w1;
            __syncthreads();
#pragma unroll 4
            for (int jj = 0; jj < 32; jj++) {
                float4 ka = *(const float4*)&bufA[jj][td];
                float4 vb = *(const float4*)&bufB[jj][te2];
                float ar[4] = {ka.x,ka.y,ka.z,ka.w};
                float br[4] = {vb.x,vb.y,vb.z,vb.w};
#pragma unroll
                for (int x = 0; x < 4; x++)
#pragma unroll
                    for (int y = 0; y < 4; y++)
                        sacc[x][y] += ar[x] * br[y];
            }
            __syncthreads();
        }
#pragma unroll
        for (int x = 0; x < 4; x++)
#pragma unroll
            for (int y = 0; y < 4; y++)
                state[td + x][te2 + y] = state[td + x][te2 + y] * wC + sacc[x][y];
        __syncthreads();
    }
    for (int idx = tid; idx < 4096; idx += 256) {
        int d = idx >> 6, e = idx & 63;
        state_out[((size_t)(b * NH + h) * 64 + d) * 64 + e] = state[d][e];
    }
}

// ---------------- per-head LN (in place on g_att) ----------------
__global__ void lnx_kernel(const float* __restrict__ sc,
                           const float* __restrict__ bi)
{
    int w = blockIdx.x * 8 + (threadIdx.x >> 5);
    int lid = threadIdx.x & 31;
    int h = w & 31;
    size_t row = (size_t)(w >> 5);
    float* p = g_att + row * DM + h * 64;
    float x0 = p[lid], x1 = p[lid + 32];
    float s = x0 + x1, q = x0 * x0 + x1 * x1;
#pragma unroll
    for (int o = 16; o > 0; o >>= 1) {
        s += __shfl_xor_sync(0xffffffffu, s, o);
        q += __shfl_xor_sync(0xffffffffu, q, o);
    }
    float mu  = s * (1.f / 64.f);
    float inv = rsqrtf(q * (1.f / 64.f) - mu * mu + 1e-5f);
    p[lid]      = (x0 - mu) * inv * sc[h * 64 + lid]      + bi[h * 64 + lid];
    p[lid + 32] = (x1 - mu) * inv * sc[h * 64 + lid + 32] + bi[h * 64 + lid + 32];
}

// ---------------- launch ----------------
extern "C" void kernel_launch(void* const* d_in, const int* in_sizes, int n_in,
                              void* d_out, int out_size)
{
    const float* inputs = (const float*)d_in[0];
    const float* tmr    = (const float*)d_in[1];
    const float* tmk    = (const float*)d_in[2];
    const float* tmv    = (const float*)d_in[3];
    const float* Wk     = (const float*)d_in[4];
    const float* Wv     = (const float*)d_in[5];
    const float* Wr     = (const float*)d_in[6];
    const float* Wo     = (const float*)d_in[7];
    const float* tdcy   = (const float*)d_in[8];
    const float* tfirst = (const float*)d_in[9];
    const float* ln1s   = (const float*)d_in[10];
    const float* ln1b   = (const float*)d_in[11];
    const float* lnxs   = (const float*)d_in[12];
    const float* lnxb   = (const float*)d_in[13];

    float* out0      = (float*)d_out;
    float* out_xlast = out0 + (size_t)BZ * SEQ * DM;
    float* out_state = out_xlast + (size_t)BZ * DM;

    ln1_kernel<<<MROWS, 256>>>(inputs, ln1s, ln1b, out_xlast);
    mix_kernel<<<(MROWS * (DM / 4)) / 256, 256>>>((const float4*)tmr,
                                                  (const float4*)tmk,
                                                  (const float4*)tmv);
    dim3 g(DM / 128, MROWS / 128);
    sgemm_kernel<0><<<g, 256>>>(Wr, nullptr, nullptr);
    sgemm_kernel<1><<<g, 256>>>(Wk, nullptr, nullptr);
    sgemm_kernel<2><<<g, 256>>>(Wv, nullptr, nullptr);
    rkw_kernel<<<dim3(2, 2, BZ * NC * NH), 256>>>(tdcy, tfirst);
    sep_kernel<<<BZ * NC * NH, 256>>>();
    scan_kernel<<<BZ * NH, 256>>>(tdcy, out_state);
    lnx_kernel<<<(MROWS * NH) / 8, 256>>>(lnxs, lnxb);
    sgemm_kernel<3><<<g, 256>>>(Wo, inputs, out0);
}

// round 2
// speedup vs baseline: 1.3369x; 1.3369x over previous
#include <cuda_runtime.h>

#define SEQ   2048
#define DM    2048
#define NH    32
#define DH    64
#define CK    128
#define NC    16
#define BZ    4
#define MROWS (BZ*SEQ)   // 8192

// ---------------- scratch (device globals; no allocation) ----------------
__device__ float g_xn [BZ*SEQ*DM];
__device__ float g_rx [BZ*SEQ*DM];
__device__ float g_kx [BZ*SEQ*DM];
__device__ float g_vx [BZ*SEQ*DM];
__device__ float g_r  [BZ*SEQ*DM];
__device__ float g_k  [BZ*SEQ*DM];
__device__ float g_v  [BZ*SEQ*DM];
__device__ float g_att[BZ*SEQ*DM];
__device__ float g_rkw[(size_t)BZ*NC*NH*CK*CK];   // 33.5M floats

// ---------------- LN over D_MODEL, also emits xn[:, -1, :] ----------------
__global__ void ln1_kernel(const float* __restrict__ x,
                           const float* __restrict__ sc,
                           const float* __restrict__ bi,
                           float* __restrict__ xlast)
{
    int row = blockIdx.x;                 // b*SEQ + t
    const float* xr = x + (size_t)row * DM;
    float* yr = g_xn + (size_t)row * DM;
    float vals[8];
    float s = 0.f, q = 0.f;
#pragma unroll
    for (int i = 0; i < 8; i++) {
        float v = xr[threadIdx.x + i * 256];
        vals[i] = v; s += v; q += v * v;
    }
#pragma unroll
    for (int o = 16; o > 0; o >>= 1) {
        s += __shfl_xor_sync(0xffffffffu, s, o);
        q += __shfl_xor_sync(0xffffffffu, q, o);
    }
    __shared__ float rs[8], rq[8];
    int w = threadIdx.x >> 5;
    if ((threadIdx.x & 31) == 0) { rs[w] = s; rq[w] = q; }
    __syncthreads();
    s = 0.f; q = 0.f;
#pragma unroll
    for (int i = 0; i < 8; i++) { s += rs[i]; q += rq[i]; }
    float mu  = s * (1.f / DM);
    float inv = rsqrtf(q * (1.f / DM) - mu * mu + 1e-5f);
    bool last = ((row & (SEQ - 1)) == SEQ - 1);
#pragma unroll
    for (int i = 0; i < 8; i++) {
        int c = threadIdx.x + i * 256;
        float y = (vals[i] - mu) * inv * sc[c] + bi[c];
        yr[c] = y;
        if (last) xlast[(row >> 11) * DM + c] = y;
    }
}

// ---------------- token-shift mixing ----------------
__global__ void mix_kernel(const float4* __restrict__ tmr,
                           const float4* __restrict__ tmk,
                           const float4* __restrict__ tmv)
{
    long i = (long)blockIdx.x * blockDim.x + threadIdx.x;   // float4 index
    const float4* xn4 = (const float4*)g_xn;
    int col = (int)(i & 511);
    long t  = (i >> 9) & (SEQ - 1);
    float4 cur = xn4[i];
    float4 prv = (t == 0) ? make_float4(0.f,0.f,0.f,0.f) : xn4[i - 512];
    float4 mr = tmr[col], mk = tmk[col], mv = tmv[col];
    float4 o;
    o.x = cur.x*mr.x + (1.f-mr.x)*prv.x;
    o.y = cur.y*mr.y + (1.f-mr.y)*prv.y;
    o.z = cur.z*mr.z + (1.f-mr.z)*prv.z;
    o.w = cur.w*mr.w + (1.f-mr.w)*prv.w;
    ((float4*)g_rx)[i] = o;
    o.x = cur.x*mk.x + (1.f-mk.x)*prv.x;
    o.y = cur.y*mk.y + (1.f-mk.y)*prv.y;
    o.z = cur.z*mk.z + (1.f-mk.z)*prv.z;
    o.w = cur.w*mk.w + (1.f-mk.w)*prv.w;
    ((float4*)g_kx)[i] = o;
    o.x = cur.x*mv.x + (1.f-mv.x)*prv.x;
    o.y = cur.y*mv.y + (1.f-mv.y)*prv.y;
    o.z = cur.z*mv.z + (1.f-mv.z)*prv.z;
    o.w = cur.w*mv.w + (1.f-mv.w)*prv.w;
    ((float4*)g_vx)[i] = o;
}

// ---------------- tf32 tensor-core GEMM ----------------
__device__ __forceinline__ unsigned f2tf(float v)
{
    unsigned r;
    asm("cvt.rna.tf32.f32 %0, %1;" : "=r"(r) : "f"(v));
    return r;
}

__device__ __forceinline__ void mma_tf32(float* c, const unsigned* a, const unsigned* b)
{
    asm volatile(
        "mma.sync.aligned.m16n8k8.row.col.f32.tf32.tf32.f32 "
        "{%0,%1,%2,%3}, {%4,%5,%6,%7}, {%8,%9}, {%0,%1,%2,%3};"
        : "+f"(c[0]), "+f"(c[1]), "+f"(c[2]), "+f"(c[3])
        : "r"(a[0]), "r"(a[1]), "r"(a[2]), "r"(a[3]),
          "r"(b[0]), "r"(b[1]));
}

// 128x128 block tile, BK=16, 4 warps (2x2), warp tile 64x64.
// MODE 0: g_rx@W -> g_r | 1: g_kx@W -> g_k | 2: g_vx@W -> g_v
// MODE 3: g_att@W + Add -> Out
template<int MODE>
__global__ void __launch_bounds__(128) tgemm_kernel(const float* __restrict__ W,
                                                    const float* __restrict__ Add,
                                                    float* __restrict__ Out)
{
    const float* A;
    float* C;
    if constexpr (MODE == 0) { A = g_rx; C = g_r; }
    else if constexpr (MODE == 1) { A = g_kx; C = g_k; }
    else if constexpr (MODE == 2) { A = g_vx; C = g_v; }
    else { A = g_att; C = Out; }

    __shared__ float As[2][128][20];    // stride 20: frag-LDS + STS.128 conflict-free
    __shared__ float Bs[2][16][136];    // stride 136: frag-LDS + STS.128 conflict-free

    int tid = threadIdx.x, lane = tid & 31, warp = tid >> 5;
    int wm = (warp >> 1) * 64, wn = (warp & 1) * 64;
    int bm = blockIdx.y * 128, bn = blockIdx.x * 128;
    int r0 = lane >> 2, c0 = lane & 3;

    const float* Ag = A + (size_t)(bm + tid) * DM;          // one row per thread
    int bblk = tid & 31, brow = (tid >> 5) * 4;             // B: 32 col-blks x 4 rows
    const float* Bg = W + (size_t)brow * DM + bn + bblk * 4;

    float4 ra[4], rb[4];
#pragma unroll
    for (int m = 0; m < 4; m++) ra[m] = *(const float4*)(Ag + m * 4);
#pragma unroll
    for (int q = 0; q < 4; q++) rb[q] = *(const float4*)(Bg + (size_t)q * DM);

    float acc[4][8][4];
#pragma unroll
    for (int i = 0; i < 4; i++)
#pragma unroll
        for (int j = 0; j < 8; j++)
#pragma unroll
            for (int e = 0; e < 4; e++) acc[i][j][e] = 0.f;

    // stash tile 0
    {
#pragma unroll
        for (int m = 0; m < 4; m++) {
            float4 v;
            v.x = __uint_as_float(f2tf(ra[m].x));
            v.y = __uint_as_float(f2tf(ra[m].y));
            v.z = __uint_as_float(f2tf(ra[m].z));
            v.w = __uint_as_float(f2tf(ra[m].w));
            *(float4*)&As[0][tid][m * 4] = v;
        }
#pragma unroll
        for (int q = 0; q < 4; q++) {
            float4 v;
            v.x = __uint_as_float(f2tf(rb[q].x));
            v.y = __uint_as_float(f2tf(rb[q].y));
            v.z = __uint_as_float(f2tf(rb[q].z));
            v.w = __uint_as_float(f2tf(rb[q].w));
            *(float4*)&Bs[0][brow + q][bblk * 4] = v;
        }
    }
    __syncthreads();

    const int NKT = DM / 16;   // 128
    for (int kt = 0; kt < NKT; kt++) {
        int buf = kt & 1;
        if (kt < NKT - 1) {
            const float* Agn = Ag + (kt + 1) * 16;
            const float* Bgn = Bg + (size_t)(kt + 1) * 16 * DM;
#pragma unroll
            for (int m = 0; m < 4; m++) ra[m] = *(const float4*)(Agn + m * 4);
#pragma unroll
            for (int q = 0; q < 4; q++) rb[q] = *(const float4*)(Bgn + (size_t)q * DM);
        }
#pragma unroll
        for (int ks = 0; ks < 2; ks++) {
            int k0 = ks * 8;
            unsigned af[4][4], bf[8][2];
#pragma unroll
            for (int i = 0; i < 4; i++) {
                af[i][0] = __float_as_uint(As[buf][wm + i * 16 + r0    ][k0 + c0    ]);
                af[i][1] = __float_as_uint(As[buf][wm + i * 16 + r0 + 8][k0 + c0    ]);
                af[i][2] = __float_as_uint(As[buf][wm + i * 16 + r0    ][k0 + c0 + 4]);
                af[i][3] = __float_as_uint(As[buf][wm + i * 16 + r0 + 8][k0 + c0 + 4]);
            }
#pragma unroll
            for (int j = 0; j < 8; j++) {
                bf[j][0] = __float_as_uint(Bs[buf][k0 + c0    ][wn + j * 8 + r0]);
                bf[j][1] = __float_as_uint(Bs[buf][k0 + c0 + 4][wn + j * 8 + r0]);
            }
#pragma unroll
            for (int i = 0; i < 4; i++)
#pragma unroll
                for (int j = 0; j < 8; j++)
                    mma_tf32(acc[i][j], af[i], bf[j]);
        }
        if (kt < NKT - 1) {
            int nb = buf ^ 1;
#pragma unroll
            for (int m = 0; m < 4; m++) {
                float4 v;
                v.x = __uint_as_float(f2tf(ra[m].x));
                v.y = __uint_as_float(f2tf(ra[m].y));
                v.z = __uint_as_float(f2tf(ra[m].z));
                v.w = __uint_as_float(f2tf(ra[m].w));
                *(float4*)&As[nb][tid][m * 4] = v;
            }
#pragma unroll
            for (int q = 0; q < 4; q++) {
                float4 v;
                v.x = __uint_as_float(f2tf(rb[q].x));
                v.y = __uint_as_float(f2tf(rb[q].y));
                v.z = __uint_as_float(f2tf(rb[q].z));
                v.w = __uint_as_float(f2tf(rb[q].w));
                *(float4*)&Bs[nb][brow + q][bblk * 4] = v;
            }
        }
        __syncthreads();
    }

    // epilogue
#pragma unroll
    for (int i = 0; i < 4; i++) {
        int row = bm + wm + i * 16 + r0;
#pragma unroll
        for (int j = 0; j < 8; j++) {
            int col = bn + wn + j * 8 + c0 * 2;
            size_t o0 = (size_t)row * DM + col;
            size_t o1 = (size_t)(row + 8) * DM + col;
            float2 v0 = make_float2(acc[i][j][0], acc[i][j][1]);
            float2 v1 = make_float2(acc[i][j][2], acc[i][j][3]);
            if constexpr (MODE == 3) {
                float2 a0 = *(const float2*)(Add + o0);
                float2 a1 = *(const float2*)(Add + o1);
                v0.x += a0.x; v0.y += a0.y;
                v1.x += a1.x; v1.y += a1.y;
            }
            *(float2*)(C + o0) = v0;
            *(float2*)(C + o1) = v1;
        }
    }
}

// ---------------- rkw = (r @ k^T) * mask, per (b,chunk,head), 64x64 tiles --
__global__ void rkw_kernel(const float* __restrict__ tdcy,
                           const float* __restrict__ tfirst)
{
    int jt = blockIdx.x, it = blockIdx.y, bch = blockIdx.z;
    int h = bch & 31;
    int chunk = (bch >> 5) & 15;
    int b = bch >> 9;
    __shared__ float rs[64][68];   // [d][i]
    __shared__ float ks[64][68];   // [d][j]
    int tid = threadIdx.x;
    int lrow = tid >> 2;           // 0..63
    int lc4  = (tid & 3) * 16;     // d start
    size_t rbase = ((size_t)(b*SEQ + chunk*CK + it*64 + lrow)) * DM + h*64 + lc4;
    size_t kbase = ((size_t)(b*SEQ + chunk*CK + jt*64 + lrow)) * DM + h*64 + lc4;
#pragma unroll
    for (int m = 0; m < 4; m++) {
        float4 rv = *(const float4*)(g_r + rbase + m * 4);
        float4 kv = *(const float4*)(g_k + kbase + m * 4);
        int d = lc4 + m * 4;
        rs[d+0][lrow] = rv.x; rs[d+1][lrow] = rv.y; rs[d+2][lrow] = rv.z; rs[d+3][lrow] = rv.w;
        ks[d+0][lrow] = kv.x; ks[d+1][lrow] = kv.y; ks[d+2][lrow] = kv.z; ks[d+3][lrow] = kv.w;
    }
    __syncthreads();
    int tx = tid & 15, ty = tid >> 4;
    float acc[4][4] = {};
#pragma unroll 8
    for (int d = 0; d < 64; d++) {
        float4 a = *(const float4*)&rs[d][ty * 4];
        float4 bq = *(const float4*)&ks[d][tx * 4];
        float ar[4] = {a.x,a.y,a.z,a.w};
        float br[4] = {bq.x,bq.y,bq.z,bq.w};
#pragma unroll
        for (int x = 0; x < 4; x++)
#pragma unroll
            for (int y = 0; y < 4; y++)
                acc[x][y] += ar[x] * br[y];
    }
    float logw = -expf(tdcy[h]);
    float u    =  expf(tfirst[h]);
#pragma unroll
    for (int x = 0; x < 4; x++)
#pragma unroll
        for (int y = 0; y < 4; y++) {
            int i = it * 64 + ty * 4 + x;
            int j = jt * 64 + tx * 4 + y;
            float m;
            if (i > j)      m = expf(logw * (float)(i - j - 1));
            else if (i == j) m = u;
            else             m = 0.f;
            g_rkw[((size_t)bch * CK + i) * CK + j] = acc[x][y] * m;
        }
}

// ---------------- sep = rkw @ v, per (b,chunk,head) ----------------
__global__ void sep_kernel()
{
    int bch = blockIdx.x;
    int h = bch & 31;
    int chunk = (bch >> 5) & 15;
    int b = bch >> 9;
    int tid = threadIdx.x;
    __shared__ float vs[128][64];
    __shared__ float rk[16][132];   // [jj][i]
    {
        int row = tid >> 1, e0 = (tid & 1) * 32;
        size_t base = ((size_t)(b*SEQ + chunk*CK + row)) * DM + h*64 + e0;
#pragma unroll
        for (int m = 0; m < 8; m++)
            *(float4*)&vs[row][e0 + m * 4] = *(const float4*)(g_v + base + m * 4);
    }
    int ty = tid >> 3, tx = tid & 7;   // ty: 0..31 row groups, tx: 0..7 col groups
    float acc[4][8] = {};
    int rrow = tid >> 1, jc = (tid & 1) * 8;
    for (int s = 0; s < 8; s++) {
        const float* src = g_rkw + ((size_t)bch * CK + rrow) * CK + s * 16 + jc;
        float4 r0 = *(const float4*)src;
        float4 r1 = *(const float4*)(src + 4);
        __syncthreads();    // protect prev-iter readers of rk (also orders vs on s==0)
        rk[jc+0][rrow] = r0.x; rk[jc+1][rrow] = r0.y; rk[jc+2][rrow] = r0.z; rk[jc+3][rrow] = r0.w;
        rk[jc+4][rrow] = r1.x; rk[jc+5][rrow] = r1.y; rk[jc+6][rrow] = r1.z; rk[jc+7][rrow] = r1.w;
        __syncthreads();
#pragma unroll
        for (int jj = 0; jj < 16; jj++) {
            float4 a  = *(const float4*)&rk[jj][ty * 4];
            float4 b0 = *(const float4*)&vs[s * 16 + jj][tx * 8];
            float4 b1 = *(const float4*)&vs[s * 16 + jj][tx * 8 + 4];
            float ar[4] = {a.x,a.y,a.z,a.w};
            float br[8] = {b0.x,b0.y,b0.z,b0.w,b1.x,b1.y,b1.z,b1.w};
#pragma unroll
            for (int x = 0; x < 4; x++)
#pragma unroll
                for (int e = 0; e < 8; e++)
                    acc[x][e] += ar[x] * br[e];
        }
    }
    size_t obase = ((size_t)(b*SEQ + chunk*CK)) * DM + h*64;
#pragma unroll
    for (int x = 0; x < 4; x++) {
        size_t ro = obase + (size_t)(ty * 4 + x) * DM + tx * 8;
        float4 o0, o1;
        o0.x = acc[x][0]; o0.y = acc[x][1]; o0.z = acc[x][2]; o0.w = acc[x][3];
        o1.x = acc[x][4]; o1.y = acc[x][5]; o1.z = acc[x][6]; o1.w = acc[x][7];
        *(float4*)(g_att + ro)     = o0;
        *(float4*)(g_att + ro + 4) = o1;
    }
}

// ---------------- sequential chunk scan per (b,head) ----------------
__global__ void scan_kernel(const float* __restrict__ tdcy,
                            float* __restrict__ state_out)
{
    int bh = blockIdx.x;
    int h = bh & 31, b = bh >> 5;
    int tid = threadIdx.x;
    __shared__ float state[64][65];
    __shared__ float bufA[32][68];
    __shared__ float bufB[32][68];
    float logw = -expf(tdcy[h]);
    float wC = expf(logw * 128.f);
    for (int idx = tid; idx < 64 * 64; idx += 256)
        state[idx >> 6][idx & 63] = 0.f;
    __syncthreads();
    int lrow = tid >> 3, lcol = (tid & 7) * 8;
    int td = (tid >> 4) * 4, te2 = (tid & 15) * 4;
    for (int c = 0; c < NC; c++) {
        size_t base = ((size_t)(b*SEQ + c*CK)) * DM + h * 64;
        // ---- bias = (r @ state) * w^i added into att (old state) ----
        for (int s4 = 0; s4 < 4; s4++) {
            const float* src = g_r + base + (size_t)(s4 * 32 + lrow) * DM + lcol;
            float4 v0 = *(const float4*)src;
            float4 v1 = *(const float4*)(src + 4);
            *(float4*)&bufA[lrow][lcol]     = v0;
            *(float4*)&bufA[lrow][lcol + 4] = v1;
            __syncthreads();
            float acc[8] = {};
            int ti = tid >> 3, te = (tid & 7) * 8;
#pragma unroll 8
            for (int d = 0; d < 64; d++) {
                float rv = bufA[ti][d];
#pragma unroll
                for (int e = 0; e < 8; e++)
                    acc[e] += rv * state[d][te + e];
            }
            float wi = expf(logw * (float)(s4 * 32 + ti));
            float* dst = g_att + base + (size_t)(s4 * 32 + ti) * DM + te;
            float4 o0 = *(float4*)dst;
            float4 o1 = *(float4*)(dst + 4);
            o0.x += wi * acc[0]; o0.y += wi * acc[1]; o0.z += wi * acc[2]; o0.w += wi * acc[3];
            o1.x += wi * acc[4]; o1.y += wi * acc[5]; o1.z += wi * acc[6]; o1.w += wi * acc[7];
            *(float4*)dst = o0;
            *(float4*)(dst + 4) = o1;
            __syncthreads();
        }
        // ---- state = state*w^C + (k * w^{C-1-j})^T @ v ----
        float sacc[4][4] = {};
        for (int s4 = 0; s4 < 4; s4++) {
            int j = s4 * 32 + lrow;
            float wk = expf(logw * (float)(127 - j));
            const float* ksrc = g_k + base + (size_t)j * DM + lcol;
            const float* vsrc = g_v + base + (size_t)j * DM + lcol;
            float4 k0 = *(const float4*)ksrc;
            float4 k1 = *(const float4*)(ksrc + 4);
            float4 w0 = *(const float4*)vsrc;
            float4 w1 = *(const float4*)(vsrc + 4);
            k0.x *= wk; k0.y *= wk; k0.z *= wk; k0.w *= wk;
            k1.x *= wk; k1.y *= wk; k1.z *= wk; k1.w *= wk;
            *(float4*)&bufA[lrow][lcol]     = k0;
            *(float4*)&bufA[lrow][lcol + 4] = k1;
            *(float4*)&bufB[lrow][lcol]     = w0;
            *(float4*)&bufB[lrow][lcol + 4] = w1;
            __syncthreads();
#pragma unroll 4
            for (int jj = 0; jj < 32; jj++) {
                float4 ka = *(const float4*)&bufA[jj][td];
                float4 vb = *(const float4*)&bufB[jj][te2];
                float ar[4] = {ka.x,ka.y,ka.z,ka.w};
                float br[4] = {vb.x,vb.y,vb.z,vb.w};
#pragma unroll
                for (int x = 0; x < 4; x++)
#pragma unroll
                    for (int y = 0; y < 4; y++)
                        sacc[x][y] += ar[x] * br[y];
            }
            __syncthreads();
        }
#pragma unroll
        for (int x = 0; x < 4; x++)
#pragma unroll
            for (int y = 0; y < 4; y++)
                state[td + x][te2 + y] = state[td + x][te2 + y] * wC + sacc[x][y];
        __syncthreads();
    }
    for (int idx = tid; idx < 4096; idx += 256) {
        int d = idx >> 6, e = idx & 63;
        state_out[((size_t)(b * NH + h) * 64 + d) * 64 + e] = state[d][e];
    }
}

// ---------------- per-head LN (in place on g_att) ----------------
__global__ void lnx_kernel(const float* __restrict__ sc,
                           const float* __restrict__ bi)
{
    int w = blockIdx.x * 8 + (threadIdx.x >> 5);
    int lid = threadIdx.x & 31;
    int h = w & 31;
    size_t row = (size_t)(w >> 5);
    float* p = g_att + row * DM + h * 64;
    float x0 = p[lid], x1 = p[lid + 32];
    float s = x0 + x1, q = x0 * x0 + x1 * x1;
#pragma unroll
    for (int o = 16; o > 0; o >>= 1) {
        s += __shfl_xor_sync(0xffffffffu, s, o);
        q += __shfl_xor_sync(0xffffffffu, q, o);
    }
    float mu  = s * (1.f / 64.f);
    float inv = rsqrtf(q * (1.f / 64.f) - mu * mu + 1e-5f);
    p[lid]      = (x0 - mu) * inv * sc[h * 64 + lid]      + bi[h * 64 + lid];
    p[lid + 32] = (x1 - mu) * inv * sc[h * 64 + lid + 32] + bi[h * 64 + lid + 32];
}

// ---------------- launch ----------------
extern "C" void kernel_launch(void* const* d_in, const int* in_sizes, int n_in,
                              void* d_out, int out_size)
{
    const float* inputs = (const float*)d_in[0];
    const float* tmr    = (const float*)d_in[1];
    const float* tmk    = (const float*)d_in[2];
    const float* tmv    = (const float*)d_in[3];
    const float* Wk     = (const float*)d_in[4];
    const float* Wv     = (const float*)d_in[5];
    const float* Wr     = (const float*)d_in[6];
    const float* Wo     = (const float*)d_in[7];
    const float* tdcy   = (const float*)d_in[8];
    const float* tfirst = (const float*)d_in[9];
    const float* ln1s   = (const float*)d_in[10];
    const float* ln1b   = (const float*)d_in[11];
    const float* lnxs   = (const float*)d_in[12];
    const float* lnxb   = (const float*)d_in[13];

    float* out0      = (float*)d_out;
    float* out_xlast = out0 + (size_t)BZ * SEQ * DM;
    float* out_state = out_xlast + (size_t)BZ * DM;

    ln1_kernel<<<MROWS, 256>>>(inputs, ln1s, ln1b, out_xlast);
    mix_kernel<<<(MROWS * (DM / 4)) / 256, 256>>>((const float4*)tmr,
                                                  (const float4*)tmk,
                                                  (const float4*)tmv);
    dim3 g(DM / 128, MROWS / 128);
    tgemm_kernel<0><<<g, 128>>>(Wr, nullptr, nullptr);
    tgemm_kernel<1><<<g, 128>>>(Wk, nullptr, nullptr);
    tgemm_kernel<2><<<g, 128>>>(Wv, nullptr, nullptr);
    rkw_kernel<<<dim3(2, 2, BZ * NC * NH), 256>>>(tdcy, tfirst);
    sep_kernel<<<BZ * NC * NH, 256>>>();
    scan_kernel<<<BZ * NH, 256>>>(tdcy, out_state);
    lnx_kernel<<<(MROWS * NH) / 8, 256>>>(lnxs, lnxb);
    tgemm_kernel<3><<<g, 128>>>(Wo, inputs, out0);
}

// round 5
// speedup vs baseline: 2.5168x; 1.8825x over previous
#include <cuda_runtime.h>
#include <cstdint>

#define SEQ   2048
#define DM    2048
#define NH    32
#define DH    64
#define CK    128
#define NC    16
#define BZ    4
#define MROWS (BZ*SEQ)   // 8192
#define STAGES 3
#define NKT   (DM/16)    // 128

// ---------------- scratch (device globals; no allocation) ----------------
__device__ float g_xn [BZ*SEQ*DM];
__device__ float g_rx [BZ*SEQ*DM];
__device__ float g_kx [BZ*SEQ*DM];
__device__ float g_vx [BZ*SEQ*DM];
__device__ float g_r  [BZ*SEQ*DM];
__device__ float g_k  [BZ*SEQ*DM];
__device__ float g_v  [BZ*SEQ*DM];
__device__ float g_att[BZ*SEQ*DM];
__device__ float g_rkw[(size_t)BZ*NC*NH*CK*CK];
__device__ float g_wtr[DM*DM];
__device__ float g_wtk[DM*DM];
__device__ float g_wtv[DM*DM];
__device__ float g_wto[DM*DM];

// ---------------- small PTX helpers ----------------
__device__ __forceinline__ unsigned f2tf(float v)
{
    unsigned r;
    asm("cvt.rna.tf32.f32 %0, %1;" : "=r"(r) : "f"(v));
    return r;
}
__device__ __forceinline__ float roundtf(float v) { return __uint_as_float(f2tf(v)); }

__device__ __forceinline__ uint32_t smem_u32(const void* p)
{
    uint32_t a;
    asm("{ .reg .u64 t; cvta.to.shared.u64 t, %1; cvt.u32.u64 %0, t; }" : "=r"(a) : "l"(p));
    return a;
}
template<int N> __device__ __forceinline__ void cp_wait()
{
    asm volatile("cp.async.wait_group %0;" :: "n"(N) : "memory");
}
__device__ __forceinline__ void cp16(uint32_t dst, const void* src)
{
    asm volatile("cp.async.cg.shared.global [%0], [%1], 16;" :: "r"(dst), "l"(src));
}
__device__ __forceinline__ void cp_commit()
{
    asm volatile("cp.async.commit_group;" ::: "memory");
}
__device__ __forceinline__ void mma_tf32(float* c, const unsigned* a, const unsigned* b)
{
    asm volatile(
        "mma.sync.aligned.m16n8k8.row.col.f32.tf32.tf32.f32 "
        "{%0,%1,%2,%3}, {%4,%5,%6,%7}, {%8,%9}, {%0,%1,%2,%3};"
        : "+f"(c[0]), "+f"(c[1]), "+f"(c[2]), "+f"(c[3])
        : "r"(a[0]), "r"(a[1]), "r"(a[2]), "r"(a[3]),
          "r"(b[0]), "r"(b[1]));
}

// ---------------- LN over D_MODEL, also emits xn[:, -1, :] ----------------
__global__ void ln1_kernel(const float* __restrict__ x,
                           const float* __restrict__ sc,
                           const float* __restrict__ bi,
                           float* __restrict__ xlast)
{
    int row = blockIdx.x;
    const float* xr = x + (size_t)row * DM;
    float* yr = g_xn + (size_t)row * DM;
    float vals[8];
    float s = 0.f, q = 0.f;
#pragma unroll
    for (int i = 0; i < 8; i++) {
        float v = xr[threadIdx.x + i * 256];
        vals[i] = v; s += v; q += v * v;
    }
#pragma unroll
    for (int o = 16; o > 0; o >>= 1) {
        s += __shfl_xor_sync(0xffffffffu, s, o);
        q += __shfl_xor_sync(0xffffffffu, q, o);
    }
    __shared__ float rs[8], rq[8];
    int w = threadIdx.x >> 5;
    if ((threadIdx.x & 31) == 0) { rs[w] = s; rq[w] = q; }
    __syncthreads();
    s = 0.f; q = 0.f;
#pragma unroll
    for (int i = 0; i < 8; i++) { s += rs[i]; q += rq[i]; }
    float mu  = s * (1.f / DM);
    float inv = rsqrtf(q * (1.f / DM) - mu * mu + 1e-5f);
    bool last = ((row & (SEQ - 1)) == SEQ - 1);
#pragma unroll
    for (int i = 0; i < 8; i++) {
        int c = threadIdx.x + i * 256;
        float y = (vals[i] - mu) * inv * sc[c] + bi[c];
        yr[c] = y;
        if (last) xlast[(row >> 11) * DM + c] = y;
    }
}

// ---------------- token-shift mixing (outputs rounded to tf32) ----------------
__global__ void mix_kernel(const float4* __restrict__ tmr,
                           const float4* __restrict__ tmk,
                           const float4* __restrict__ tmv)
{
    long i = (long)blockIdx.x * blockDim.x + threadIdx.x;
    const float4* xn4 = (const float4*)g_xn;
    int col = (int)(i & 511);
    long t  = (i >> 9) & (SEQ - 1);
    float4 cur = xn4[i];
    float4 prv = (t == 0) ? make_float4(0.f,0.f,0.f,0.f) : xn4[i - 512];
    float4 mr = tmr[col], mk = tmk[col], mv = tmv[col];
    float4 o;
    o.x = roundtf(cur.x*mr.x + (1.f-mr.x)*prv.x);
    o.y = roundtf(cur.y*mr.y + (1.f-mr.y)*prv.y);
    o.z = roundtf(cur.z*mr.z + (1.f-mr.z)*prv.z);
    o.w = roundtf(cur.w*mr.w + (1.f-mr.w)*prv.w);
    ((float4*)g_rx)[i] = o;
    o.x = roundtf(cur.x*mk.x + (1.f-mk.x)*prv.x);
    o.y = roundtf(cur.y*mk.y + (1.f-mk.y)*prv.y);
    o.z = roundtf(cur.z*mk.z + (1.f-mk.z)*prv.z);
    o.w = roundtf(cur.w*mk.w + (1.f-mk.w)*prv.w);
    ((float4*)g_kx)[i] = o;
    o.x = roundtf(cur.x*mv.x + (1.f-mv.x)*prv.x);
    o.y = roundtf(cur.y*mv.y + (1.f-mv.y)*prv.y);
    o.z = roundtf(cur.z*mv.z + (1.f-mv.z)*prv.z);
    o.w = roundtf(cur.w*mv.w + (1.f-mv.w)*prv.w);
    ((float4*)g_vx)[i] = o;
}

// ---------------- weight transpose (and tf32 rounding) ----------------
__global__ void transpose_kernel(const float* __restrict__ src, float* __restrict__ dst)
{
    __shared__ float t[32][33];
    int bx = blockIdx.x * 32, by = blockIdx.y * 32;
#pragma unroll
    for (int i = 0; i < 4; i++)
        t[threadIdx.y + i * 8][threadIdx.x] =
            src[(size_t)(by + threadIdx.y + i * 8) * DM + bx + threadIdx.x];
    __syncthreads();
#pragma unroll
    for (int i = 0; i < 4; i++)
        dst[(size_t)(bx + threadIdx.y + i * 8) * DM + by + threadIdx.x] =
            roundtf(t[threadIdx.x][threadIdx.y + i * 8]);
}

// ---------------- tf32 mma.sync GEMM, cp.async 3-stage ----------------
// C[8192x2048] = A @ Bt^T   (A row-major [m][k], Bt row-major [n][k], both tf32-rounded)
// 256 threads, block tile 128x128x16, 8 warps as 2(m) x 4(n) -> warp tile 64x32
#define ASTRIDE 20                      // floats per smem row (16 data + 4 pad)
#define STG_FLOATS (2 * 128 * ASTRIDE)  // A tile + B tile per stage = 5120 floats

template<int MODE>
__global__ void __launch_bounds__(256, 2) tgemm_kernel(const float* __restrict__ Bt,
                                                       const float* __restrict__ Add,
                                                       float* __restrict__ Out)
{
    const float* A;
    float* C;
    if constexpr (MODE == 0) { A = g_rx; C = g_r; }
    else if constexpr (MODE == 1) { A = g_kx; C = g_k; }
    else if constexpr (MODE == 2) { A = g_vx; C = g_v; }
    else { A = g_att; C = Out; }

    extern __shared__ float smem[];
    uint32_t sb = smem_u32(smem);
    int tid = threadIdx.x, lane = tid & 31, warp = tid >> 5;
    int r0 = lane >> 2, c0 = lane & 3;
    int wm = (warp >> 2) * 64, wn = (warp & 3) * 32;
    int bm = blockIdx.y * 128, bn = blockIdx.x * 128;

    const float* Ag = A  + (size_t)bm * DM;
    const float* Bg = Bt + (size_t)bn * DM;

    int cm = tid >> 1, cko = (tid & 1) * 8;   // copy: row, k-offset
    auto copy_stage = [&](int buf, int kt) {
        uint32_t sA = sb + buf * (STG_FLOATS * 4);
        uint32_t sB = sA + 128 * ASTRIDE * 4;
        const float* Ac = Ag + kt * 16 + (size_t)cm * DM + cko;
        const float* Bc = Bg + kt * 16 + (size_t)cm * DM + cko;
        uint32_t off = cm * (ASTRIDE * 4) + cko * 4;
        cp16(sA + off,      Ac);
        cp16(sA + off + 16, Ac + 4);
        cp16(sB + off,      Bc);
        cp16(sB + off + 16, Bc + 4);
        cp_commit();
    };

    float acc[4][4][4];
#pragma unroll
    for (int i = 0; i < 4; i++)
#pragma unroll
        for (int j = 0; j < 4; j++)
#pragma unroll
            for (int e = 0; e < 4; e++) acc[i][j][e] = 0.f;

    copy_stage(0, 0);
    copy_stage(1, 1);
    cp_wait<1>();
    __syncthreads();

    for (int kt = 0; kt < NKT; kt++) {
        int buf = kt % 3;
        const float* As = smem + buf * STG_FLOATS;
        const float* Bs = As + 128 * ASTRIDE;
#pragma unroll
        for (int ks = 0; ks < 2; ks++) {
            int k0 = ks * 8;
            unsigned af[4][4], bf[4][2];
#pragma unroll
            for (int i = 0; i < 4; i++) {
                int m0 = (wm + i * 16 + r0) * ASTRIDE + k0 + c0;
                af[i][0] = __float_as_uint(As[m0]);
                af[i][1] = __float_as_uint(As[m0 + 8 * ASTRIDE]);
                af[i][2] = __float_as_uint(As[m0 + 4]);
                af[i][3] = __float_as_uint(As[m0 + 8 * ASTRIDE + 4]);
            }
#pragma unroll
            for (int j = 0; j < 4; j++) {
                int n0 = (wn + j * 8 + r0) * ASTRIDE + k0 + c0;
                bf[j][0] = __float_as_uint(Bs[n0]);
                bf[j][1] = __float_as_uint(Bs[n0 + 4]);
            }
#pragma unroll
            for (int i = 0; i < 4; i++)
#pragma unroll
                for (int j = 0; j < 4; j++)
                    mma_tf32(acc[i][j], af[i], bf[j]);
        }
        // Keep exactly one commit-group per iteration so cp_wait<1> always
        // guarantees tile kt+1 is resident (empty group in the tail —
        // this closes the R4 tail race that corrupted the last K-tiles).
        if (kt + 2 < NKT) copy_stage((kt + 2) % 3, kt + 2);
        else              cp_commit();
        cp_wait<1>();
        __syncthreads();
    }

    // epilogue: direct register -> global (float2 per mma half-row)
#pragma unroll
    for (int i = 0; i < 4; i++) {
        int row = bm + wm + i * 16 + r0;
#pragma unroll
        for (int j = 0; j < 4; j++) {
            int col = bn + wn + j * 8 + c0 * 2;
            size_t o0 = (size_t)row * DM + col;
            size_t o1 = (size_t)(row + 8) * DM + col;
            float2 v0 = make_float2(acc[i][j][0], acc[i][j][1]);
            float2 v1 = make_float2(acc[i][j][2], acc[i][j][3]);
            if constexpr (MODE == 3) {
                float2 a0 = *(const float2*)(Add + o0);
                float2 a1 = *(const float2*)(Add + o1);
                v0.x += a0.x; v0.y += a0.y;
                v1.x += a1.x; v1.y += a1.y;
            }
            *(float2*)(C + o0) = v0;
            *(float2*)(C + o1) = v1;
        }
    }
}

// ---------------- rkw = (r @ k^T) * mask, per (b,chunk,head), 64x64 tiles --
__global__ void rkw_kernel(const float* __restrict__ tdcy,
                           const float* __restrict__ tfirst)
{
    int jt = blockIdx.x, it = blockIdx.y, bch = blockIdx.z;
    int h = bch & 31;
    int chunk = (bch >> 5) & 15;
    int b = bch >> 9;
    __shared__ float rs[64][68];
    __shared__ float ks[64][68];
    int tid = threadIdx.x;
    int lrow = tid >> 2;
    int lc4  = (tid & 3) * 16;
    size_t rbase = ((size_t)(b*SEQ + chunk*CK + it*64 + lrow)) * DM + h*64 + lc4;
    size_t kbase = ((size_t)(b*SEQ + chunk*CK + jt*64 + lrow)) * DM + h*64 + lc4;
#pragma unroll
    for (int m = 0; m < 4; m++) {
        float4 rv = *(const float4*)(g_r + rbase + m * 4);
        float4 kv = *(const float4*)(g_k + kbase + m * 4);
        int d = lc4 + m * 4;
        rs[d+0][lrow] = rv.x; rs[d+1][lrow] = rv.y; rs[d+2][lrow] = rv.z; rs[d+3][lrow] = rv.w;
        ks[d+0][lrow] = kv.x; ks[d+1][lrow] = kv.y; ks[d+2][lrow] = kv.z; ks[d+3][lrow] = kv.w;
    }
    __syncthreads();
    int tx = tid & 15, ty = tid >> 4;
    float acc[4][4] = {};
#pragma unroll 8
    for (int d = 0; d < 64; d++) {
        float4 a = *(const float4*)&rs[d][ty * 4];
        float4 bq = *(const float4*)&ks[d][tx * 4];
        float ar[4] = {a.x,a.y,a.z,a.w};
        float br[4] = {bq.x,bq.y,bq.z,bq.w};
#pragma unroll
        for (int x = 0; x < 4; x++)
#pragma unroll
            for (int y = 0; y < 4; y++)
                acc[x][y] += ar[x] * br[y];
    }
    float logw = -expf(tdcy[h]);
    float u    =  expf(tfirst[h]);
#pragma unroll
    for (int x = 0; x < 4; x++)
#pragma unroll
        for (int y = 0; y < 4; y++) {
            int i = it * 64 + ty * 4 + x;
            int j = jt * 64 + tx * 4 + y;
            float m;
            if (i > j)      m = expf(logw * (float)(i - j - 1));
            else if (i == j) m = u;
            else             m = 0.f;
            g_rkw[((size_t)bch * CK + i) * CK + j] = acc[x][y] * m;
        }
}

// ---------------- sep = rkw @ v, per (b,chunk,head) ----------------
__global__ void sep_kernel()
{
    int bch = blockIdx.x;
    int h = bch & 31;
    int chunk = (bch >> 5) & 15;
    int b = bch >> 9;
    int tid = threadIdx.x;
    __shared__ float vs[128][64];
    __shared__ float rk[16][132];
    {
        int row = tid >> 1, e0 = (tid & 1) * 32;
        size_t base = ((size_t)(b*SEQ + chunk*CK + row)) * DM + h*64 + e0;
#pragma unroll
        for (int m = 0; m < 8; m++)
            *(float4*)&vs[row][e0 + m * 4] = *(const float4*)(g_v + base + m * 4);
    }
    int ty = tid >> 3, tx = tid & 7;
    float acc[4][8] = {};
    int rrow = tid >> 1, jc = (tid & 1) * 8;
    for (int s = 0; s < 8; s++) {
        const float* src = g_rkw + ((size_t)bch * CK + rrow) * CK + s * 16 + jc;
        float4 r0 = *(const float4*)src;
        float4 r1 = *(const float4*)(src + 4);
        __syncthreads();
        rk[jc+0][rrow] = r0.x; rk[jc+1][rrow] = r0.y; rk[jc+2][rrow] = r0.z; rk[jc+3][rrow] = r0.w;
        rk[jc+4][rrow] = r1.x; rk[jc+5][rrow] = r1.y; rk[jc+6][rrow] = r1.z; rk[jc+7][rrow] = r1.w;
        __syncthreads();
#pragma unroll
        for (int jj = 0; jj < 16; jj++) {
            float4 a  = *(const float4*)&rk[jj][ty * 4];
            float4 b0 = *(const float4*)&vs[s * 16 + jj][tx * 8];
            float4 b1 = *(const float4*)&vs[s * 16 + jj][tx * 8 + 4];
            float ar[4] = {a.x,a.y,a.z,a.w};
            float br[8] = {b0.x,b0.y,b0.z,b0.w,b1.x,b1.y,b1.z,b1.w};
#pragma unroll
            for (int x = 0; x < 4; x++)
#pragma unroll
                for (int e = 0; e < 8; e++)
                    acc[x][e] += ar[x] * br[e];
        }
    }
    size_t obase = ((size_t)(b*SEQ + chunk*CK)) * DM + h*64;
#pragma unroll
    for (int x = 0; x < 4; x++) {
        size_t ro = obase + (size_t)(ty * 4 + x) * DM + tx * 8;
        float4 o0, o1;
        o0.x = acc[x][0]; o0.y = acc[x][1]; o0.z = acc[x][2]; o0.w = acc[x][3];
        o1.x = acc[x][4]; o1.y = acc[x][5]; o1.z = acc[x][6]; o1.w = acc[x][7];
        *(float4*)(g_att + ro)     = o0;
        *(float4*)(g_att + ro + 4) = o1;
    }
}

// ---------------- sequential chunk scan per (b,head) ----------------
__global__ void scan_kernel(const float* __restrict__ tdcy,
                            float* __restrict__ state_out)
{
    int bh = blockIdx.x;
    int h = bh & 31, b = bh >> 5;
    int tid = threadIdx.x;
    __shared__ float state[64][65];
    __shared__ float bufA[32][68];
    __shared__ float bufB[32][68];
    float logw = -expf(tdcy[h]);
    float wC = expf(logw * 128.f);
    for (int idx = tid; idx < 64 * 64; idx += 256)
        state[idx >> 6][idx & 63] = 0.f;
    __syncthreads();
    int lrow = tid >> 3, lcol = (tid & 7) * 8;
    int td = (tid >> 4) * 4, te2 = (tid & 15) * 4;
    for (int c = 0; c < NC; c++) {
        size_t base = ((size_t)(b*SEQ + c*CK)) * DM + h * 64;
        for (int s4 = 0; s4 < 4; s4++) {
            const float* src = g_r + base + (size_t)(s4 * 32 + lrow) * DM + lcol;
            float4 v0 = *(const float4*)src;
            float4 v1 = *(const float4*)(src + 4);
            *(float4*)&bufA[lrow][lcol]     = v0;
            *(float4*)&bufA[lrow][lcol + 4] = v1;
            __syncthreads();
            float acc[8] = {};
            int ti = tid >> 3, te = (tid & 7) * 8;
#pragma unroll 8
            for (int d = 0; d < 64; d++) {
                float rv = bufA[ti][d];
#pragma unroll
                for (int e = 0; e < 8; e++)
                    acc[e] += rv * state[d][te + e];
            }
            float wi = expf(logw * (float)(s4 * 32 + ti));
            float* dst = g_att + base + (size_t)(s4 * 32 + ti) * DM + te;
            float4 o0 = *(float4*)dst;
            float4 o1 = *(float4*)(dst + 4);
            o0.x += wi * acc[0]; o0.y += wi * acc[1]; o0.z += wi * acc[2]; o0.w += wi * acc[3];
            o1.x += wi * acc[4]; o1.y += wi * acc[5]; o1.z += wi * acc[6]; o1.w += wi * acc[7];
            *(float4*)dst = o0;
            *(float4*)(dst + 4) = o1;
            __syncthreads();
        }
        float sacc[4][4] = {};
        for (int s4 = 0; s4 < 4; s4++) {
            int j = s4 * 32 + lrow;
            float wk = expf(logw * (float)(127 - j));
            const float* ksrc = g_k + base + (size_t)j * DM + lcol;
            const float* vsrc = g_v + base + (size_t)j * DM + lcol;
            float4 k0 = *(const float4*)ksrc;
            float4 k1 = *(const float4*)(ksrc + 4);
            float4 w0 = *(const float4*)vsrc;
            float4 w1 = *(const float4*)(vsrc + 4);
            k0.x *= wk; k0.y *= wk; k0.z *= wk; k0.w *= wk;
            k1.x *= wk; k1.y *= wk; k1.z *= wk; k1.w *= wk;
            *(float4*)&bufA[lrow][lcol]     = k0;
            *(float4*)&bufA[lrow][lcol + 4] = k1;
            *(float4*)&bufB[lrow][lcol]     = w0;
            *(float4*)&bufB[lrow][lcol + 4] = w1;
            __syncthreads();
#pragma unroll 4
            for (int jj = 0; jj < 32; jj++) {
                float4 ka = *(const float4*)&bufA[jj][td];
                float4 vb = *(const float4*)&bufB[jj][te2];
                float ar[4] = {ka.x,ka.y,ka.z,ka.w};
                float br[4] = {vb.x,vb.y,vb.z,vb.w};
#pragma unroll
                for (int x = 0; x < 4; x++)
#pragma unroll
                    for (int y = 0; y < 4; y++)
                        sacc[x][y] += ar[x] * br[y];
            }
            __syncthreads();
        }
#pragma unroll
        for (int x = 0; x < 4; x++)
#pragma unroll
            for (int y = 0; y < 4; y++)
                state[td + x][te2 + y] = state[td + x][te2 + y] * wC + sacc[x][y];
        __syncthreads();
    }
    for (int idx = tid; idx < 4096; idx += 256) {
        int d = idx >> 6, e = idx & 63;
        state_out[((size_t)(b * NH + h) * 64 + d) * 64 + e] = state[d][e];
    }
}

// ---------------- per-head LN (in place on g_att, output rounded to tf32) ----
__global__ void lnx_kernel(const float* __restrict__ sc,
                           const float* __restrict__ bi)
{
    int w = blockIdx.x * 8 + (threadIdx.x >> 5);
    int lid = threadIdx.x & 31;
    int h = w & 31;
    size_t row = (size_t)(w >> 5);
    float* p = g_att + row * DM + h * 64;
    float x0 = p[lid], x1 = p[lid + 32];
    float s = x0 + x1, q = x0 * x0 + x1 * x1;
#pragma unroll
    for (int o = 16; o > 0; o >>= 1) {
        s += __shfl_xor_sync(0xffffffffu, s, o);
        q += __shfl_xor_sync(0xffffffffu, q, o);
    }
    float mu  = s * (1.f / 64.f);
    float inv = rsqrtf(q * (1.f / 64.f) - mu * mu + 1e-5f);
    p[lid]      = roundtf((x0 - mu) * inv * sc[h * 64 + lid]      + bi[h * 64 + lid]);
    p[lid + 32] = roundtf((x1 - mu) * inv * sc[h * 64 + lid + 32] + bi[h * 64 + lid + 32]);
}

// ---------------- launch ----------------
extern "C" void kernel_launch(void* const* d_in, const int* in_sizes, int n_in,
                              void* d_out, int out_size)
{
    const float* inputs = (const float*)d_in[0];
    const float* tmr    = (const float*)d_in[1];
    const float* tmk    = (const float*)d_in[2];
    const float* tmv    = (const float*)d_in[3];
    const float* Wk     = (const float*)d_in[4];
    const float* Wv     = (const float*)d_in[5];
    const float* Wr     = (const float*)d_in[6];
    const float* Wo     = (const float*)d_in[7];
    const float* tdcy   = (const float*)d_in[8];
    const float* tfirst = (const float*)d_in[9];
    const float* ln1s   = (const float*)d_in[10];
    const float* ln1b   = (const float*)d_in[11];
    const float* lnxs   = (const float*)d_in[12];
    const float* lnxb   = (const float*)d_in[13];

    float* out0      = (float*)d_out;
    float* out_xlast = out0 + (size_t)BZ * SEQ * DM;
    float* out_state = out_xlast + (size_t)BZ * DM;

    const int GSMEM = STAGES * STG_FLOATS * 4;   // 61440 B
    cudaFuncSetAttribute(tgemm_kernel<0>, cudaFuncAttributeMaxDynamicSharedMemorySize, GSMEM);
    cudaFuncSetAttribute(tgemm_kernel<1>, cudaFuncAttributeMaxDynamicSharedMemorySize, GSMEM);
    cudaFuncSetAttribute(tgemm_kernel<2>, cudaFuncAttributeMaxDynamicSharedMemorySize, GSMEM);
    cudaFuncSetAttribute(tgemm_kernel<3>, cudaFuncAttributeMaxDynamicSharedMemorySize, GSMEM);

    float* wtr; float* wtk; float* wtv; float* wto;
    cudaGetSymbolAddress((void**)&wtr, g_wtr);
    cudaGetSymbolAddress((void**)&wtk, g_wtk);
    cudaGetSymbolAddress((void**)&wtv, g_wtv);
    cudaGetSymbolAddress((void**)&wto, g_wto);

    dim3 tg(64, 64), tb(32, 8);
    transpose_kernel<<<tg, tb>>>(Wr, wtr);
    transpose_kernel<<<tg, tb>>>(Wk, wtk);
    transpose_kernel<<<tg, tb>>>(Wv, wtv);
    transpose_kernel<<<tg, tb>>>(Wo, wto);

    ln1_kernel<<<MROWS, 256>>>(inputs, ln1s, ln1b, out_xlast);
    mix_kernel<<<(MROWS * (DM / 4)) / 256, 256>>>((const float4*)tmr,
                                                  (const float4*)tmk,
                                                  (const float4*)tmv);
    dim3 g(DM / 128, MROWS / 128);
    tgemm_kernel<0><<<g, 256, GSMEM>>>(wtr, nullptr, nullptr);
    tgemm_kernel<1><<<g, 256, GSMEM>>>(wtk, nullptr, nullptr);
    tgemm_kernel<2><<<g, 256, GSMEM>>>(wtv, nullptr, nullptr);
    rkw_kernel<<<dim3(2, 2, BZ * NC * NH), 256>>>(tdcy, tfirst);
    sep_kernel<<<BZ * NC * NH, 256>>>();
    scan_kernel<<<BZ * NH, 256>>>(tdcy, out_state);
    lnx_kernel<<<(MROWS * NH) / 8, 256>>>(lnxs, lnxb);
    tgemm_kernel<3><<<g, 256, GSMEM>>>(wto, inputs, out0);
}